// round 15
// baseline (speedup 1.0000x reference)
#include <cuda_runtime.h>
#include <math.h>
#include <stdint.h>
#include <mma.h>
#include <cuda_fp16.h>

using namespace nvcuda;

#define BB 8
#define CC 256
#define SS 16384
#define EPSV 1e-5f
#define KSPLIT 16

// ---------------- scratch ----------------
__device__ __half g_Xh[(size_t)BB*CC*SS];   // 67 MB hi
__device__ __half g_Xl[(size_t)BB*CC*SS];   // 67 MB lo
__device__ __half g_Mh[(size_t)BB*CC*CC];   // M+I hi
__device__ __half g_Ml[(size_t)BB*CC*CC];   // M+I lo
__device__ float g_Gp[(size_t)KSPLIT*BB*CC*CC];
__device__ float g_G [BB*CC*CC];
__device__ float g_P [BB*CC*CC];
__device__ float g_L [BB*CC*CC];
__device__ float g_Aq[CC*CC];
__device__ float g_Ak[CC*CC];
__device__ float g_AvT[CC*CC];
__device__ float g_bq[CC];
__device__ float g_bk[CC];
__device__ float g_bv[CC];
__device__ float g_s [BB*CC];
__device__ float g_u [BB*CC];
__device__ float g_w [BB*CC];
__device__ float g_cv[BB*CC];

// ---------------- helpers ----------------
__device__ __forceinline__ void split2h(float v, __half& h, __half& l) {
    h = __float2half_rn(v);
    l = __float2half_rn(v - __half2float(h));
}
__device__ __forceinline__ uint32_t smem_u32(const void* p) {
    uint32_t a;
    asm("{ .reg .u64 t; cvta.to.shared.u64 t, %1; cvt.u32.u64 %0, t; }" : "=r"(a) : "l"(p));
    return a;
}
#define CP_A16(dst, src) asm volatile("cp.async.cg.shared.global [%0], [%1], 16;" :: "r"(dst), "l"(src) : "memory")
#define CP_COMMIT()      asm volatile("cp.async.commit_group;" ::: "memory")
#define CP_WAIT(n)       asm volatile("cp.async.wait_group %0;" :: "n"(n) : "memory")

// ---------------- reductions ----------------
__device__ __forceinline__ float blockReduceSum(float v) {
    __shared__ float sh[8];
    int lane = threadIdx.x & 31, wid = threadIdx.x >> 5;
#pragma unroll
    for (int o = 16; o; o >>= 1) v += __shfl_xor_sync(0xffffffffu, v, o);
    if (lane == 0) sh[wid] = v;
    __syncthreads();
    float r = 0.f;
#pragma unroll
    for (int i = 0; i < 8; i++) r += sh[i];
    __syncthreads();
    return r;
}
__device__ __forceinline__ float blockReduceMax(float v) {
    __shared__ float sh[8];
    int lane = threadIdx.x & 31, wid = threadIdx.x >> 5;
#pragma unroll
    for (int o = 16; o; o >>= 1) v = fmaxf(v, __shfl_xor_sync(0xffffffffu, v, o));
    if (lane == 0) sh[wid] = v;
    __syncthreads();
    float r = -3.402823466e38f;
#pragma unroll
    for (int i = 0; i < 8; i++) r = fmaxf(r, sh[i]);
    __syncthreads();
    return r;
}

// ---------------- prep ----------------
__global__ void prep_kernel(
    const float* __restrict__ Wk, const float* __restrict__ kg, const float* __restrict__ kb,
    const float* __restrict__ km, const float* __restrict__ kvv,
    const float* __restrict__ Wq, const float* __restrict__ qg, const float* __restrict__ qb,
    const float* __restrict__ qm, const float* __restrict__ qv,
    const float* __restrict__ Wv, const float* __restrict__ vg, const float* __restrict__ vb,
    const float* __restrict__ vm, const float* __restrict__ vv)
{
    int o = blockIdx.x, m = blockIdx.y, i = threadIdx.x;
    const float *W, *ga, *be, *me, *va;
    if (m == 0)      { W = Wq; ga = qg; be = qb; me = qm; va = qv; }
    else if (m == 1) { W = Wk; ga = kg; be = kb; me = km; va = kvv; }
    else             { W = Wv; ga = vg; be = vb; me = vm; va = vv; }
    float inv = ga[o] / sqrtf(va[o] + EPSV);
    float a = inv * W[o*CC + i];
    if (m == 0)      { g_Aq[o*CC + i] = a;  if (i == 0) g_bq[o] = be[o] - me[o]*inv; }
    else if (m == 1) { g_Ak[o*CC + i] = a;  if (i == 0) g_bk[o] = be[o] - me[o]*inv; }
    else             { g_AvT[i*CC + o] = a; if (i == 0) g_bv[o] = be[o] - me[o]*inv; }
}

// ---------------- presplit: X -> (Xh, Xl) halves in GMEM, fused rowsum ----------------
__global__ void __launch_bounds__(256) presplit_kernel(const float* __restrict__ x) {
    int c = blockIdx.x, n = blockIdx.y, t = threadIdx.x;
    size_t base = ((size_t)n*CC + c)*SS;
    const float4* xr = (const float4*)(x + base);
    ushort4* xh = (ushort4*)(g_Xh + base);
    ushort4* xl = (ushort4*)(g_Xl + base);
    float acc = 0.f;
    for (int i = t; i < SS/4; i += 256) {
        float4 v = xr[i];
        acc += (v.x + v.y) + (v.z + v.w);
        __half hx, lx, hy, ly, hz, lz, hw, lw;
        split2h(v.x, hx, lx); split2h(v.y, hy, ly);
        split2h(v.z, hz, lz); split2h(v.w, hw, lw);
        ushort4 uh, ul;
        uh.x = __half_as_ushort(hx); uh.y = __half_as_ushort(hy);
        uh.z = __half_as_ushort(hz); uh.w = __half_as_ushort(hw);
        ul.x = __half_as_ushort(lx); ul.y = __half_as_ushort(ly);
        ul.z = __half_as_ushort(lz); ul.w = __half_as_ushort(lw);
        xh[i] = uh;
        xl[i] = ul;
    }
    float tot = blockReduceSum(acc);
    if (t == 0) g_s[n*CC + c] = tot;
}

// ---------------- gram: 3xFP16 WMMA, pre-split operands, cp.async staging ----------------
#define GLDH 40
#define GBUF (128*GLDH*2)                 /* bytes per half-buffer = 10240 */
#define GSTGB (4*GBUF)                    /* bytes per stage = 40960 */
#define GRAM_SMEM (2*GSTGB)               /* 81920 B */
__global__ void __launch_bounds__(256, 2) gram_wmma_kernel() {
    extern __shared__ char smraw[];
    const uint32_t smb = smem_u32(smraw);
    const int bx = blockIdx.x;                 // 0:(0,0) 1:(0,1) 2:(1,1)
    const int bi = (bx == 2) ? 1 : 0;
    const int bj = (bx == 0) ? 0 : 1;
    const bool diag = (bi == bj);

    const int tid = threadIdx.x, w = tid >> 5;
    const int wm = w >> 1, wn = w & 1;         // 4x2 warps -> 32x64 tiles
    const int zk = blockIdx.y, n = blockIdx.z;
    const int s0 = zk * (SS / KSPLIT);

    const int row = tid >> 1, part = tid & 1;
    const size_t aoff = ((size_t)n*CC + bi*128 + row)*SS + s0 + part*16;
    const size_t boff = ((size_t)n*CC + bj*128 + row)*SS + s0 + part*16;
    const uint32_t toff = (uint32_t)(row*GLDH*2 + part*32);

    wmma::fragment<wmma::accumulator, 16, 16, 16, float> acc[2][4];
#pragma unroll
    for (int i = 0; i < 2; i++)
#pragma unroll
        for (int j = 0; j < 4; j++) wmma::fill_fragment(acc[i][j], 0.0f);

    const int NT = SS/KSPLIT/32;   // 32

    auto issue = [&](int st, int t) {
        uint32_t base = smb + st*GSTGB + toff;
        CP_A16(base,               g_Xh + aoff + t*32);
        CP_A16(base + 16,          g_Xh + aoff + t*32 + 8);
        CP_A16(base + GBUF,        g_Xl + aoff + t*32);
        CP_A16(base + GBUF + 16,   g_Xl + aoff + t*32 + 8);
        if (!diag) {
            CP_A16(base + 2*GBUF,      g_Xh + boff + t*32);
            CP_A16(base + 2*GBUF + 16, g_Xh + boff + t*32 + 8);
            CP_A16(base + 3*GBUF,      g_Xl + boff + t*32);
            CP_A16(base + 3*GBUF + 16, g_Xl + boff + t*32 + 8);
        }
        CP_COMMIT();
    };

    auto domma = [&](int st) {
        __half* Ah = (__half*)(smraw + st*GSTGB);
        __half* Al = Ah + 128*GLDH;
        __half* Bh = diag ? Ah : (Al + 128*GLDH);
        __half* Bl = diag ? Al : (Al + 2*128*GLDH);
#pragma unroll
        for (int ks = 0; ks < 2; ks++) {
            wmma::fragment<wmma::matrix_a, 16, 16, 16, __half, wmma::row_major> ah[2], al[2];
            wmma::fragment<wmma::matrix_b, 16, 16, 16, __half, wmma::col_major> bh[4], bl[4];
#pragma unroll
            for (int i = 0; i < 2; i++) {
                wmma::load_matrix_sync(ah[i], &Ah[(wm*32 + i*16)*GLDH + ks*16], GLDH);
                wmma::load_matrix_sync(al[i], &Al[(wm*32 + i*16)*GLDH + ks*16], GLDH);
            }
#pragma unroll
            for (int j = 0; j < 4; j++) {
                wmma::load_matrix_sync(bh[j], &Bh[(wn*64 + j*16)*GLDH + ks*16], GLDH);
                wmma::load_matrix_sync(bl[j], &Bl[(wn*64 + j*16)*GLDH + ks*16], GLDH);
            }
            // term-major ordering: 8 independent MMAs between writes to the same acc
#pragma unroll
            for (int i = 0; i < 2; i++)
#pragma unroll
                for (int j = 0; j < 4; j++) wmma::mma_sync(acc[i][j], ah[i], bl[j], acc[i][j]);
#pragma unroll
            for (int i = 0; i < 2; i++)
#pragma unroll
                for (int j = 0; j < 4; j++) wmma::mma_sync(acc[i][j], al[i], bh[j], acc[i][j]);
#pragma unroll
            for (int i = 0; i < 2; i++)
#pragma unroll
                for (int j = 0; j < 4; j++) wmma::mma_sync(acc[i][j], ah[i], bh[j], acc[i][j]);
        }
    };

    issue(0, 0);
    for (int t = 0; t < NT; t++) {
        if (t + 1 < NT) { issue((t + 1) & 1, t + 1); CP_WAIT(1); }
        else            { CP_WAIT(0); }
        __syncthreads();
        domma(t & 1);
        __syncthreads();
    }

    float* gp = g_Gp + ((size_t)zk*BB + n)*CC*CC;
#pragma unroll
    for (int i = 0; i < 2; i++)
#pragma unroll
        for (int j = 0; j < 4; j++) {
            wmma::store_matrix_sync(
                gp + (size_t)(bi*128 + wm*32 + i*16)*CC + bj*128 + wn*64 + j*16,
                acc[i][j], CC, wmma::mem_row_major);
            if (!diag)
                wmma::store_matrix_sync(
                    gp + (size_t)(bj*128 + wn*64 + j*16)*CC + bi*128 + wm*32 + i*16,
                    acc[i][j], CC, wmma::mem_col_major);
        }
}

// ---------------- reduce gram partials ----------------
__global__ void reduceG_kernel() {
    size_t i = (size_t)blockIdx.x*256 + threadIdx.x;
    float s = 0.f;
#pragma unroll
    for (int z = 0; z < KSPLIT; z++) s += g_Gp[(size_t)z*(BB*CC*CC) + i];
    g_G[i] = s;
}

// ---------------- middle chain: 256^3 NT GEMM, 32x64 tiles (256 CTAs, 2/SM) ----------------
// mode 2 writes M+I pre-split into g_Mh/g_Ml
__global__ void __launch_bounds__(256) gemm256_nt_kernel(int mode) {
    __shared__ float As[16*32];
    __shared__ float Bs[16*64];
    int bj = blockIdx.x, bi = blockIdx.y, n = blockIdx.z;   // bj<4 (64 cols), bi<8 (32 rows)
    int tid = threadIdx.x, tx = tid & 15, ty = tid >> 4;
    int arow = tid >> 3, ac2 = tid & 7;
    int brow = tid >> 2, bc4 = tid & 3;

    const float* A; const float* Bm; float* Out;
    if (mode == 0)      { A = g_Aq;                  Bm = g_G + (size_t)n*CC*CC; Out = g_P + (size_t)n*CC*CC; }
    else if (mode == 1) { A = g_P + (size_t)n*CC*CC; Bm = g_Ak;                  Out = g_L + (size_t)n*CC*CC; }
    else                { A = g_L + (size_t)n*CC*CC; Bm = g_AvT;                 Out = 0; }

    const float* ap = A  + (size_t)(bi*32 + arow)*CC + ac2*2;
    const float* bp = Bm + (size_t)(bj*64 + brow)*CC + bc4*4;

    float acc[2][4] = {};
    float2 a = *(const float2*)ap;
    float4 b = *(const float4*)bp;

    for (int kc = 0; kc < CC; kc += 16) {
        As[(ac2*2+0)*32 + arow] = a.x;
        As[(ac2*2+1)*32 + arow] = a.y;
        Bs[(bc4*4+0)*64 + brow] = b.x;
        Bs[(bc4*4+1)*64 + brow] = b.y;
        Bs[(bc4*4+2)*64 + brow] = b.z;
        Bs[(bc4*4+3)*64 + brow] = b.w;
        __syncthreads();
        int kn = (kc + 16 < CC) ? kc + 16 : kc;
        a = *(const float2*)(ap + kn);
        b = *(const float4*)(bp + kn);
#pragma unroll
        for (int kk = 0; kk < 16; kk++) {
            float2 av = *(const float2*)&As[kk*32 + ty*2];
            float4 bv = *(const float4*)&Bs[kk*64 + tx*4];
            acc[0][0] += av.x*bv.x; acc[0][1] += av.x*bv.y; acc[0][2] += av.x*bv.z; acc[0][3] += av.x*bv.w;
            acc[1][0] += av.y*bv.x; acc[1][1] += av.y*bv.y; acc[1][2] += av.y*bv.z; acc[1][3] += av.y*bv.w;
        }
        __syncthreads();
    }

    int row = bi*32 + ty*2, col = bj*64 + tx*4;
    if (mode == 1) {
#pragma unroll
        for (int u = 0; u < 2; u++) {
            float uu = g_u[n*CC + row + u], bb = g_bq[row + u];
#pragma unroll
            for (int v = 0; v < 4; v++) {
                float bk = g_bk[col + v];
                acc[u][v] += uu*bk + bb*(g_w[n*CC + col + v] + (float)SS*bk);
            }
        }
    }

    if (mode == 2) {
        __half* mh = g_Mh + (size_t)n*CC*CC;
        __half* ml = g_Ml + (size_t)n*CC*CC;
#pragma unroll
        for (int u = 0; u < 2; u++) {
            ushort4 uh, ul;
            __half hh, ll;
#pragma unroll
            for (int v = 0; v < 4; v++) {
                float val = acc[u][v] + ((row + u == col + v) ? 1.0f : 0.0f);
                split2h(val, hh, ll);
                ((unsigned short*)&uh)[v] = __half_as_ushort(hh);
                ((unsigned short*)&ul)[v] = __half_as_ushort(ll);
            }
            *(ushort4*)(mh + (size_t)(row + u)*CC + col) = uh;
            *(ushort4*)(ml + (size_t)(row + u)*CC + col) = ul;
        }
    } else {
        float* o = Out + (size_t)row*CC + col;
#pragma unroll
        for (int u = 0; u < 2; u++)
            *(float4*)(o + (size_t)u*CC) = make_float4(acc[u][0], acc[u][1], acc[u][2], acc[u][3]);
    }
}

// ---------------- matvecs (u,w in one launch) ----------------
__global__ void matvec01_kernel() {
    int r = blockIdx.x, n = blockIdx.y, m = blockIdx.z, t = threadIdx.x;
    const float* Arow = (m == 0) ? (g_Aq + (size_t)r*CC) : (g_Ak + (size_t)r*CC);
    float* out = (m == 0) ? (g_u + n*CC + r) : (g_w + n*CC + r);
    float p = Arow[t] * g_s[n*CC + t];
    float tot = blockReduceSum(p);
    if (t == 0) *out = tot;
}

// ---------------- softmax + cv = attn @ bv fused ----------------
__global__ void softmax_kernel() {
    int r = blockIdx.x, n = blockIdx.y, t = threadIdx.x;
    float* row = g_L + ((size_t)n*CC + r)*CC;
    float v = row[t];
    float m = blockReduceMax(v);
    float e = expf(v - m);
    float ss = blockReduceSum(e);
    float a = e / ss;
    row[t] = a;
    float cv = blockReduceSum(a * g_bv[t]);
    if (t == 0) g_cv[n*CC + r] = cv;
}

// ---------------- out = (M+I) @ X + c : 3xFP16 WMMA, cp.async staging ----------------
#define MLD 40
#define XLD 136
#define OLDC 132
#define MBUF (128*MLD*2)                  /* 10240 B */
#define XBUF (32*XLD*2)                   /* 8704 B */
#define OSTGB (2*MBUF + 2*XBUF)           /* 37888 B per stage */
#define OUT_SMEM (2*OSTGB > 128*OLDC*4 ? 2*OSTGB : 128*OLDC*4)   /* 75776 */
__global__ void __launch_bounds__(256, 2) out_wmma_kernel(float* __restrict__ out) {
    extern __shared__ char smraw[];
    const uint32_t smb = smem_u32(smraw);
    float* Cs = (float*)smraw;

    const int tid = threadIdx.x, w = tid >> 5;
    const int wm = w >> 1, wn = w & 1;      // 4x2 warps -> 32x64 tiles
    const int bs = blockIdx.x, bc = blockIdx.y, n = blockIdx.z;
    const int s0 = bs*128, c0 = bc*128;

    wmma::fragment<wmma::accumulator, 16, 16, 16, float> acc[2][4];
#pragma unroll
    for (int i = 0; i < 2; i++)
#pragma unroll
        for (int j = 0; j < 4; j++) wmma::fill_fragment(acc[i][j], 0.0f);

    const int row = tid >> 1, part = tid & 1;
    const int xr = tid >> 3, xseg = tid & 7;
    const size_t mbase = (size_t)n*CC*CC + (size_t)(c0 + row)*CC + part*16;
    const uint32_t mto = (uint32_t)(row*MLD*2 + part*32);
    const uint32_t xto = (uint32_t)(xr*XLD*2 + xseg*32);

    auto issue = [&](int st, int kb) {
        uint32_t base = smb + st*OSTGB;
        CP_A16(base + mto,               g_Mh + mbase + kb);
        CP_A16(base + mto + 16,          g_Mh + mbase + kb + 8);
        CP_A16(base + MBUF + mto,        g_Ml + mbase + kb);
        CP_A16(base + MBUF + mto + 16,   g_Ml + mbase + kb + 8);
        size_t xoff = ((size_t)n*CC + kb + xr)*SS + s0 + xseg*16;
        CP_A16(base + 2*MBUF + xto,              g_Xh + xoff);
        CP_A16(base + 2*MBUF + xto + 16,         g_Xh + xoff + 8);
        CP_A16(base + 2*MBUF + XBUF + xto,       g_Xl + xoff);
        CP_A16(base + 2*MBUF + XBUF + xto + 16,  g_Xl + xoff + 8);
        CP_COMMIT();
    };

    auto domma = [&](int st) {
        __half* Mh = (__half*)(smraw + st*OSTGB);
        __half* Ml = Mh + 128*MLD;
        __half* Xh = Ml + 128*MLD;
        __half* Xl = Xh + 32*XLD;
#pragma unroll
        for (int ks = 0; ks < 2; ks++) {
            wmma::fragment<wmma::matrix_a, 16, 16, 16, __half, wmma::row_major> ah[2], al[2];
            wmma::fragment<wmma::matrix_b, 16, 16, 16, __half, wmma::row_major> bh[4], bl[4];
#pragma unroll
            for (int i = 0; i < 2; i++) {
                wmma::load_matrix_sync(ah[i], &Mh[(wm*32 + i*16)*MLD + ks*16], MLD);
                wmma::load_matrix_sync(al[i], &Ml[(wm*32 + i*16)*MLD + ks*16], MLD);
            }
#pragma unroll
            for (int j = 0; j < 4; j++) {
                wmma::load_matrix_sync(bh[j], &Xh[(ks*16)*XLD + wn*64 + j*16], XLD);
                wmma::load_matrix_sync(bl[j], &Xl[(ks*16)*XLD + wn*64 + j*16], XLD);
            }
            // term-major ordering
#pragma unroll
            for (int i = 0; i < 2; i++)
#pragma unroll
                for (int j = 0; j < 4; j++) wmma::mma_sync(acc[i][j], ah[i], bl[j], acc[i][j]);
#pragma unroll
            for (int i = 0; i < 2; i++)
#pragma unroll
                for (int j = 0; j < 4; j++) wmma::mma_sync(acc[i][j], al[i], bh[j], acc[i][j]);
#pragma unroll
            for (int i = 0; i < 2; i++)
#pragma unroll
                for (int j = 0; j < 4; j++) wmma::mma_sync(acc[i][j], ah[i], bh[j], acc[i][j]);
        }
    };

    issue(0, 0);
    const int NT = CC/32;   // 8
    for (int t = 0; t < NT; t++) {
        if (t + 1 < NT) { issue((t + 1) & 1, (t + 1)*32); CP_WAIT(1); }
        else            { CP_WAIT(0); }
        __syncthreads();
        domma(t & 1);
        __syncthreads();
    }

#pragma unroll
    for (int i = 0; i < 2; i++)
#pragma unroll
        for (int j = 0; j < 4; j++)
            wmma::store_matrix_sync(&Cs[(wm*32 + i*16)*OLDC + wn*64 + j*16],
                                    acc[i][j], OLDC, wmma::mem_row_major);
    __syncthreads();

    const int crow = tid >> 1, cpart = tid & 1;
    float cv = g_cv[n*CC + c0 + crow];
    float* op = out + ((size_t)n*CC + c0 + crow)*SS + s0 + cpart*64;
#pragma unroll
    for (int q = 0; q < 16; q++) {
        float4 v = *(float4*)&Cs[crow*OLDC + cpart*64 + q*4];
        v.x += cv; v.y += cv; v.z += cv; v.w += cv;
        *(float4*)(op + q*4) = v;
    }
}

// ---------------- launcher ----------------
extern "C" void kernel_launch(void* const* d_in, const int* in_sizes, int n_in,
                              void* d_out, int out_size) {
    const float* x   = (const float*)d_in[0];
    const float* Wk  = (const float*)d_in[1];
    const float* kg  = (const float*)d_in[2];
    const float* kb  = (const float*)d_in[3];
    const float* km  = (const float*)d_in[4];
    const float* kv  = (const float*)d_in[5];
    const float* Wq  = (const float*)d_in[6];
    const float* qg  = (const float*)d_in[7];
    const float* qb  = (const float*)d_in[8];
    const float* qm  = (const float*)d_in[9];
    const float* qv  = (const float*)d_in[10];
    const float* Wv  = (const float*)d_in[11];
    const float* vg  = (const float*)d_in[12];
    const float* vb  = (const float*)d_in[13];
    const float* vm  = (const float*)d_in[14];
    const float* vv  = (const float*)d_in[15];
    float* out = (float*)d_out;

    cudaFuncSetAttribute(gram_wmma_kernel, cudaFuncAttributeMaxDynamicSharedMemorySize, GRAM_SMEM);
    cudaFuncSetAttribute(out_wmma_kernel,  cudaFuncAttributeMaxDynamicSharedMemorySize, OUT_SMEM);

    prep_kernel<<<dim3(CC, 3), CC>>>(Wk, kg, kb, km, kv, Wq, qg, qb, qm, qv, Wv, vg, vb, vm, vv);
    presplit_kernel<<<dim3(CC, BB), 256>>>(x);                    // Xh/Xl + rowsum
    matvec01_kernel<<<dim3(CC, BB, 2), 256>>>();                  // u, w
    gram_wmma_kernel<<<dim3(3, KSPLIT, BB), 256, GRAM_SMEM>>>();  // <- profiled slot
    reduceG_kernel<<<BB*CC*CC/256, 256>>>();
    gemm256_nt_kernel<<<dim3(4, 8, BB), 256>>>(0);   // P = Aq @ G
    gemm256_nt_kernel<<<dim3(4, 8, BB), 256>>>(1);   // L = P @ Ak^T + rank-1
    softmax_kernel<<<dim3(CC, BB), 256>>>();         // attn + cv fused
    gemm256_nt_kernel<<<dim3(4, 8, BB), 256>>>(2);   // Mh/Ml = attn @ Av + I (pre-split)
    out_wmma_kernel<<<dim3(SS/128, CC/128, BB), 256, OUT_SMEM>>>(out);
}

// round 16
// speedup vs baseline: 1.1187x; 1.1187x over previous
#include <cuda_runtime.h>
#include <math.h>
#include <stdint.h>
#include <mma.h>
#include <cuda_fp16.h>

using namespace nvcuda;

#define BB 8
#define CC 256
#define SS 16384
#define EPSV 1e-5f
#define KSPLIT 16

// ---------------- scratch ----------------
__device__ __half g_Xh[(size_t)BB*CC*SS];   // 67 MB hi
__device__ __half g_Xl[(size_t)BB*CC*SS];   // 67 MB lo
__device__ __half g_Mh[(size_t)BB*CC*CC];   // M+I hi
__device__ __half g_Ml[(size_t)BB*CC*CC];   // M+I lo
__device__ float g_Gp[(size_t)KSPLIT*BB*CC*CC];
__device__ float g_G [BB*CC*CC];
__device__ float g_P [BB*CC*CC];
__device__ float g_L [BB*CC*CC];
__device__ float g_Aq[CC*CC];
__device__ float g_Ak[CC*CC];
__device__ float g_AvT[CC*CC];
__device__ float g_bq[CC];
__device__ float g_bk[CC];
__device__ float g_bv[CC];
__device__ float g_s [BB*CC];
__device__ float g_u [BB*CC];
__device__ float g_w [BB*CC];
__device__ float g_cv[BB*CC];

// ---------------- helpers ----------------
__device__ __forceinline__ void split2h(float v, __half& h, __half& l) {
    h = __float2half_rn(v);
    l = __float2half_rn(v - __half2float(h));
}
__device__ __forceinline__ uint32_t smem_u32(const void* p) {
    uint32_t a;
    asm("{ .reg .u64 t; cvta.to.shared.u64 t, %1; cvt.u32.u64 %0, t; }" : "=r"(a) : "l"(p));
    return a;
}
#define CP_A16(dst, src) asm volatile("cp.async.cg.shared.global [%0], [%1], 16;" :: "r"(dst), "l"(src) : "memory")
#define CP_COMMIT()      asm volatile("cp.async.commit_group;" ::: "memory")
#define CP_WAIT(n)       asm volatile("cp.async.wait_group %0;" :: "n"(n) : "memory")

// ---------------- reductions ----------------
__device__ __forceinline__ float blockReduceSum(float v) {
    __shared__ float sh[8];
    int lane = threadIdx.x & 31, wid = threadIdx.x >> 5;
#pragma unroll
    for (int o = 16; o; o >>= 1) v += __shfl_xor_sync(0xffffffffu, v, o);
    if (lane == 0) sh[wid] = v;
    __syncthreads();
    float r = 0.f;
#pragma unroll
    for (int i = 0; i < 8; i++) r += sh[i];
    __syncthreads();
    return r;
}
__device__ __forceinline__ float blockReduceMax(float v) {
    __shared__ float sh[8];
    int lane = threadIdx.x & 31, wid = threadIdx.x >> 5;
#pragma unroll
    for (int o = 16; o; o >>= 1) v = fmaxf(v, __shfl_xor_sync(0xffffffffu, v, o));
    if (lane == 0) sh[wid] = v;
    __syncthreads();
    float r = -3.402823466e38f;
#pragma unroll
    for (int i = 0; i < 8; i++) r = fmaxf(r, sh[i]);
    __syncthreads();
    return r;
}

// ---------------- prep ----------------
__global__ void prep_kernel(
    const float* __restrict__ Wk, const float* __restrict__ kg, const float* __restrict__ kb,
    const float* __restrict__ km, const float* __restrict__ kvv,
    const float* __restrict__ Wq, const float* __restrict__ qg, const float* __restrict__ qb,
    const float* __restrict__ qm, const float* __restrict__ qv,
    const float* __restrict__ Wv, const float* __restrict__ vg, const float* __restrict__ vb,
    const float* __restrict__ vm, const float* __restrict__ vv)
{
    int o = blockIdx.x, m = blockIdx.y, i = threadIdx.x;
    const float *W, *ga, *be, *me, *va;
    if (m == 0)      { W = Wq; ga = qg; be = qb; me = qm; va = qv; }
    else if (m == 1) { W = Wk; ga = kg; be = kb; me = km; va = kvv; }
    else             { W = Wv; ga = vg; be = vb; me = vm; va = vv; }
    float inv = ga[o] / sqrtf(va[o] + EPSV);
    float a = inv * W[o*CC + i];
    if (m == 0)      { g_Aq[o*CC + i] = a;  if (i == 0) g_bq[o] = be[o] - me[o]*inv; }
    else if (m == 1) { g_Ak[o*CC + i] = a;  if (i == 0) g_bk[o] = be[o] - me[o]*inv; }
    else             { g_AvT[i*CC + o] = a; if (i == 0) g_bv[o] = be[o] - me[o]*inv; }
}

// ---------------- presplit: X -> (Xh, Xl) halves in GMEM, fused rowsum ----------------
__global__ void __launch_bounds__(256) presplit_kernel(const float* __restrict__ x) {
    int c = blockIdx.x, n = blockIdx.y, t = threadIdx.x;
    size_t base = ((size_t)n*CC + c)*SS;
    const float4* xr = (const float4*)(x + base);
    ushort4* xh = (ushort4*)(g_Xh + base);
    ushort4* xl = (ushort4*)(g_Xl + base);
    float acc = 0.f;
    for (int i = t; i < SS/4; i += 256) {
        float4 v = xr[i];
        acc += (v.x + v.y) + (v.z + v.w);
        __half hx, lx, hy, ly, hz, lz, hw, lw;
        split2h(v.x, hx, lx); split2h(v.y, hy, ly);
        split2h(v.z, hz, lz); split2h(v.w, hw, lw);
        ushort4 uh, ul;
        uh.x = __half_as_ushort(hx); uh.y = __half_as_ushort(hy);
        uh.z = __half_as_ushort(hz); uh.w = __half_as_ushort(hw);
        ul.x = __half_as_ushort(lx); ul.y = __half_as_ushort(ly);
        ul.z = __half_as_ushort(lz); ul.w = __half_as_ushort(lw);
        xh[i] = uh;
        xl[i] = ul;
    }
    float tot = blockReduceSum(acc);
    if (t == 0) g_s[n*CC + c] = tot;
}

// ---------------- gram: 3xFP16 WMMA, pre-split operands, cp.async staging ----------------
#define GLDH 40
#define GBUF (128*GLDH*2)                 /* bytes per half-buffer = 10240 */
#define GSTGB (4*GBUF)                    /* bytes per stage = 40960 */
#define GRAM_SMEM (2*GSTGB)               /* 81920 B */
__global__ void __launch_bounds__(256, 2) gram_wmma_kernel() {
    extern __shared__ char smraw[];
    const uint32_t smb = smem_u32(smraw);
    const int bx = blockIdx.x;                 // 0:(0,0) 1:(0,1) 2:(1,1)
    const int bi = (bx == 2) ? 1 : 0;
    const int bj = (bx == 0) ? 0 : 1;
    const bool diag = (bi == bj);

    const int tid = threadIdx.x, w = tid >> 5;
    const int wm = w >> 1, wn = w & 1;         // 4x2 warps -> 32x64 tiles
    const int zk = blockIdx.y, n = blockIdx.z;
    const int s0 = zk * (SS / KSPLIT);

    const int row = tid >> 1, part = tid & 1;
    const size_t aoff = ((size_t)n*CC + bi*128 + row)*SS + s0 + part*16;
    const size_t boff = ((size_t)n*CC + bj*128 + row)*SS + s0 + part*16;
    const uint32_t toff = (uint32_t)(row*GLDH*2 + part*32);

    wmma::fragment<wmma::accumulator, 16, 16, 16, float> acc[2][4];
#pragma unroll
    for (int i = 0; i < 2; i++)
#pragma unroll
        for (int j = 0; j < 4; j++) wmma::fill_fragment(acc[i][j], 0.0f);

    const int NT = SS/KSPLIT/32;   // 32

    auto issue = [&](int st, int t) {
        uint32_t base = smb + st*GSTGB + toff;
        CP_A16(base,               g_Xh + aoff + t*32);
        CP_A16(base + 16,          g_Xh + aoff + t*32 + 8);
        CP_A16(base + GBUF,        g_Xl + aoff + t*32);
        CP_A16(base + GBUF + 16,   g_Xl + aoff + t*32 + 8);
        if (!diag) {
            CP_A16(base + 2*GBUF,      g_Xh + boff + t*32);
            CP_A16(base + 2*GBUF + 16, g_Xh + boff + t*32 + 8);
            CP_A16(base + 3*GBUF,      g_Xl + boff + t*32);
            CP_A16(base + 3*GBUF + 16, g_Xl + boff + t*32 + 8);
        }
        CP_COMMIT();
    };

    auto domma = [&](int st) {
        __half* Ah = (__half*)(smraw + st*GSTGB);
        __half* Al = Ah + 128*GLDH;
        __half* Bh = diag ? Ah : (Al + 128*GLDH);
        __half* Bl = diag ? Al : (Al + 2*128*GLDH);
#pragma unroll
        for (int ks = 0; ks < 2; ks++) {
            wmma::fragment<wmma::matrix_a, 16, 16, 16, __half, wmma::row_major> ah[2], al[2];
            wmma::fragment<wmma::matrix_b, 16, 16, 16, __half, wmma::col_major> bh[4], bl[4];
#pragma unroll
            for (int i = 0; i < 2; i++) {
                wmma::load_matrix_sync(ah[i], &Ah[(wm*32 + i*16)*GLDH + ks*16], GLDH);
                wmma::load_matrix_sync(al[i], &Al[(wm*32 + i*16)*GLDH + ks*16], GLDH);
            }
#pragma unroll
            for (int j = 0; j < 4; j++) {
                wmma::load_matrix_sync(bh[j], &Bh[(wn*64 + j*16)*GLDH + ks*16], GLDH);
                wmma::load_matrix_sync(bl[j], &Bl[(wn*64 + j*16)*GLDH + ks*16], GLDH);
            }
#pragma unroll
            for (int i = 0; i < 2; i++)
#pragma unroll
                for (int j = 0; j < 4; j++) {
                    wmma::mma_sync(acc[i][j], ah[i], bl[j], acc[i][j]);
                    wmma::mma_sync(acc[i][j], al[i], bh[j], acc[i][j]);
                    wmma::mma_sync(acc[i][j], ah[i], bh[j], acc[i][j]);
                }
        }
    };

    issue(0, 0);
    for (int t = 0; t < NT; t++) {
        if (t + 1 < NT) { issue((t + 1) & 1, t + 1); CP_WAIT(1); }
        else            { CP_WAIT(0); }
        __syncthreads();
        domma(t & 1);
        __syncthreads();
    }

    float* gp = g_Gp + ((size_t)zk*BB + n)*CC*CC;
#pragma unroll
    for (int i = 0; i < 2; i++)
#pragma unroll
        for (int j = 0; j < 4; j++) {
            wmma::store_matrix_sync(
                gp + (size_t)(bi*128 + wm*32 + i*16)*CC + bj*128 + wn*64 + j*16,
                acc[i][j], CC, wmma::mem_row_major);
            if (!diag)
                wmma::store_matrix_sync(
                    gp + (size_t)(bj*128 + wn*64 + j*16)*CC + bi*128 + wm*32 + i*16,
                    acc[i][j], CC, wmma::mem_col_major);
        }
}

// ---------------- reduce gram partials ----------------
__global__ void reduceG_kernel() {
    size_t i = (size_t)blockIdx.x*256 + threadIdx.x;
    float s = 0.f;
#pragma unroll
    for (int z = 0; z < KSPLIT; z++) s += g_Gp[(size_t)z*(BB*CC*CC) + i];
    g_G[i] = s;
}

// ---------------- middle chain: 256^3 NT GEMM (SIMT fp32, 64x64 tiles) ----------------
// mode 2 writes M+I pre-split into g_Mh/g_Ml
__global__ void __launch_bounds__(256) gemm256_nt_kernel(int mode) {
    __shared__ float As[16*64];
    __shared__ float Bs[16*64];
    int bj = blockIdx.x, bi = blockIdx.y, n = blockIdx.z;
    int tid = threadIdx.x, tx = tid & 15, ty = tid >> 4;
    int lrow = tid >> 2, lc4 = tid & 3;

    const float* A; const float* Bm; float* Out;
    if (mode == 0)      { A = g_Aq;                  Bm = g_G + (size_t)n*CC*CC; Out = g_P + (size_t)n*CC*CC; }
    else if (mode == 1) { A = g_P + (size_t)n*CC*CC; Bm = g_Ak;                  Out = g_L + (size_t)n*CC*CC; }
    else                { A = g_L + (size_t)n*CC*CC; Bm = g_AvT;                 Out = 0; }

    const float* ap = A  + (size_t)(bi*64 + lrow)*CC + lc4*4;
    const float* bp = Bm + (size_t)(bj*64 + lrow)*CC + lc4*4;

    float acc[4][4] = {};
    float4 a = *(const float4*)ap;
    float4 b = *(const float4*)bp;

    for (int kc = 0; kc < CC; kc += 16) {
        As[(lc4*4+0)*64 + lrow] = a.x;  As[(lc4*4+1)*64 + lrow] = a.y;
        As[(lc4*4+2)*64 + lrow] = a.z;  As[(lc4*4+3)*64 + lrow] = a.w;
        Bs[(lc4*4+0)*64 + lrow] = b.x;  Bs[(lc4*4+1)*64 + lrow] = b.y;
        Bs[(lc4*4+2)*64 + lrow] = b.z;  Bs[(lc4*4+3)*64 + lrow] = b.w;
        __syncthreads();
        int kn = (kc + 16 < CC) ? kc + 16 : kc;
        a = *(const float4*)(ap + kn);
        b = *(const float4*)(bp + kn);
#pragma unroll
        for (int kk = 0; kk < 16; kk++) {
            float4 av = *(const float4*)&As[kk*64 + ty*4];
            float4 bv = *(const float4*)&Bs[kk*64 + tx*4];
            acc[0][0] += av.x*bv.x; acc[0][1] += av.x*bv.y; acc[0][2] += av.x*bv.z; acc[0][3] += av.x*bv.w;
            acc[1][0] += av.y*bv.x; acc[1][1] += av.y*bv.y; acc[1][2] += av.y*bv.z; acc[1][3] += av.y*bv.w;
            acc[2][0] += av.z*bv.x; acc[2][1] += av.z*bv.y; acc[2][2] += av.z*bv.z; acc[2][3] += av.z*bv.w;
            acc[3][0] += av.w*bv.x; acc[3][1] += av.w*bv.y; acc[3][2] += av.w*bv.z; acc[3][3] += av.w*bv.w;
        }
        __syncthreads();
    }

    int row = bi*64 + ty*4, col = bj*64 + tx*4;
    if (mode == 1) {
#pragma unroll
        for (int u = 0; u < 4; u++) {
            float uu = g_u[n*CC + row + u], bb = g_bq[row + u];
#pragma unroll
            for (int v = 0; v < 4; v++) {
                float bk = g_bk[col + v];
                acc[u][v] += uu*bk + bb*(g_w[n*CC + col + v] + (float)SS*bk);
            }
        }
    }

    if (mode == 2) {
        __half* mh = g_Mh + (size_t)n*CC*CC;
        __half* ml = g_Ml + (size_t)n*CC*CC;
#pragma unroll
        for (int u = 0; u < 4; u++) {
            ushort4 uh, ul;
            __half hh, ll;
#pragma unroll
            for (int v = 0; v < 4; v++) {
                float val = acc[u][v] + ((row + u == col + v) ? 1.0f : 0.0f);
                split2h(val, hh, ll);
                ((unsigned short*)&uh)[v] = __half_as_ushort(hh);
                ((unsigned short*)&ul)[v] = __half_as_ushort(ll);
            }
            *(ushort4*)(mh + (size_t)(row + u)*CC + col) = uh;
            *(ushort4*)(ml + (size_t)(row + u)*CC + col) = ul;
        }
    } else {
        float* o = Out + (size_t)row*CC + col;
#pragma unroll
        for (int u = 0; u < 4; u++)
            *(float4*)(o + (size_t)u*CC) = make_float4(acc[u][0], acc[u][1], acc[u][2], acc[u][3]);
    }
}

// ---------------- matvecs (u,w in one launch) ----------------
__global__ void matvec01_kernel() {
    int r = blockIdx.x, n = blockIdx.y, m = blockIdx.z, t = threadIdx.x;
    const float* Arow = (m == 0) ? (g_Aq + (size_t)r*CC) : (g_Ak + (size_t)r*CC);
    float* out = (m == 0) ? (g_u + n*CC + r) : (g_w + n*CC + r);
    float p = Arow[t] * g_s[n*CC + t];
    float tot = blockReduceSum(p);
    if (t == 0) *out = tot;
}

// ---------------- softmax + cv = attn @ bv fused ----------------
__global__ void softmax_kernel() {
    int r = blockIdx.x, n = blockIdx.y, t = threadIdx.x;
    float* row = g_L + ((size_t)n*CC + r)*CC;
    float v = row[t];
    float m = blockReduceMax(v);
    float e = expf(v - m);
    float ss = blockReduceSum(e);
    float a = e / ss;
    row[t] = a;
    float cv = blockReduceSum(a * g_bv[t]);
    if (t == 0) g_cv[n*CC + r] = cv;
}

// ---------------- out = (M+I) @ X + c : 2-term FP16 WMMA (drop Mh*Xl), cp.async ----------------
#define MLD 40
#define XLD 136
#define OLDC 132
#define MBUF (128*MLD*2)                  /* 10240 B */
#define XBUF (32*XLD*2)                   /* 8704 B */
#define OSTGB (2*MBUF + XBUF)             /* 29184 B per stage (Mh, Ml, Xh only) */
#define OUT_SMEM (2*OSTGB > 128*OLDC*4 ? 2*OSTGB : 128*OLDC*4)   /* 67584 */
__global__ void __launch_bounds__(256, 2) out_wmma_kernel(float* __restrict__ out) {
    extern __shared__ char smraw[];
    const uint32_t smb = smem_u32(smraw);
    float* Cs = (float*)smraw;

    const int tid = threadIdx.x, w = tid >> 5;
    const int wm = w >> 1, wn = w & 1;      // 4x2 warps -> 32x64 tiles
    const int bs = blockIdx.x, bc = blockIdx.y, n = blockIdx.z;
    const int s0 = bs*128, c0 = bc*128;

    wmma::fragment<wmma::accumulator, 16, 16, 16, float> acc[2][4];
#pragma unroll
    for (int i = 0; i < 2; i++)
#pragma unroll
        for (int j = 0; j < 4; j++) wmma::fill_fragment(acc[i][j], 0.0f);

    const int row = tid >> 1, part = tid & 1;
    const int xr = tid >> 3, xseg = tid & 7;
    const size_t mbase = (size_t)n*CC*CC + (size_t)(c0 + row)*CC + part*16;
    const uint32_t mto = (uint32_t)(row*MLD*2 + part*32);
    const uint32_t xto = (uint32_t)(xr*XLD*2 + xseg*32);

    auto issue = [&](int st, int kb) {
        uint32_t base = smb + st*OSTGB;
        CP_A16(base + mto,               g_Mh + mbase + kb);
        CP_A16(base + mto + 16,          g_Mh + mbase + kb + 8);
        CP_A16(base + MBUF + mto,        g_Ml + mbase + kb);
        CP_A16(base + MBUF + mto + 16,   g_Ml + mbase + kb + 8);
        size_t xoff = ((size_t)n*CC + kb + xr)*SS + s0 + xseg*16;
        CP_A16(base + 2*MBUF + xto,      g_Xh + xoff);
        CP_A16(base + 2*MBUF + xto + 16, g_Xh + xoff + 8);
        CP_COMMIT();
    };

    auto domma = [&](int st) {
        __half* Mh = (__half*)(smraw + st*OSTGB);
        __half* Ml = Mh + 128*MLD;
        __half* Xh = Ml + 128*MLD;
#pragma unroll
        for (int ks = 0; ks < 2; ks++) {
            wmma::fragment<wmma::matrix_a, 16, 16, 16, __half, wmma::row_major> ah[2], al[2];
            wmma::fragment<wmma::matrix_b, 16, 16, 16, __half, wmma::row_major> bh[4];
#pragma unroll
            for (int i = 0; i < 2; i++) {
                wmma::load_matrix_sync(ah[i], &Mh[(wm*32 + i*16)*MLD + ks*16], MLD);
                wmma::load_matrix_sync(al[i], &Ml[(wm*32 + i*16)*MLD + ks*16], MLD);
            }
#pragma unroll
            for (int j = 0; j < 4; j++)
                wmma::load_matrix_sync(bh[j], &Xh[(ks*16)*XLD + wn*64 + j*16], XLD);
#pragma unroll
            for (int i = 0; i < 2; i++)
#pragma unroll
                for (int j = 0; j < 4; j++) {
                    wmma::mma_sync(acc[i][j], al[i], bh[j], acc[i][j]);
                    wmma::mma_sync(acc[i][j], ah[i], bh[j], acc[i][j]);
                }
        }
    };

    issue(0, 0);
    const int NT = CC/32;   // 8
    for (int t = 0; t < NT; t++) {
        if (t + 1 < NT) { issue((t + 1) & 1, (t + 1)*32); CP_WAIT(1); }
        else            { CP_WAIT(0); }
        __syncthreads();
        domma(t & 1);
        __syncthreads();
    }

#pragma unroll
    for (int i = 0; i < 2; i++)
#pragma unroll
        for (int j = 0; j < 4; j++)
            wmma::store_matrix_sync(&Cs[(wm*32 + i*16)*OLDC + wn*64 + j*16],
                                    acc[i][j], OLDC, wmma::mem_row_major);
    __syncthreads();

    const int crow = tid >> 1, cpart = tid & 1;
    float cv = g_cv[n*CC + c0 + crow];
    float* op = out + ((size_t)n*CC + c0 + crow)*SS + s0 + cpart*64;
#pragma unroll
    for (int q = 0; q < 16; q++) {
        float4 v = *(float4*)&Cs[crow*OLDC + cpart*64 + q*4];
        v.x += cv; v.y += cv; v.z += cv; v.w += cv;
        *(float4*)(op + q*4) = v;
    }
}

// ---------------- launcher ----------------
extern "C" void kernel_launch(void* const* d_in, const int* in_sizes, int n_in,
                              void* d_out, int out_size) {
    const float* x   = (const float*)d_in[0];
    const float* Wk  = (const float*)d_in[1];
    const float* kg  = (const float*)d_in[2];
    const float* kb  = (const float*)d_in[3];
    const float* km  = (const float*)d_in[4];
    const float* kv  = (const float*)d_in[5];
    const float* Wq  = (const float*)d_in[6];
    const float* qg  = (const float*)d_in[7];
    const float* qb  = (const float*)d_in[8];
    const float* qm  = (const float*)d_in[9];
    const float* qv  = (const float*)d_in[10];
    const float* Wv  = (const float*)d_in[11];
    const float* vg  = (const float*)d_in[12];
    const float* vb  = (const float*)d_in[13];
    const float* vm  = (const float*)d_in[14];
    const float* vv  = (const float*)d_in[15];
    float* out = (float*)d_out;

    cudaFuncSetAttribute(gram_wmma_kernel, cudaFuncAttributeMaxDynamicSharedMemorySize, GRAM_SMEM);
    cudaFuncSetAttribute(out_wmma_kernel,  cudaFuncAttributeMaxDynamicSharedMemorySize, OUT_SMEM);

    prep_kernel<<<dim3(CC, 3), CC>>>(Wk, kg, kb, km, kv, Wq, qg, qb, qm, qv, Wv, vg, vb, vm, vv);
    presplit_kernel<<<dim3(CC, BB), 256>>>(x);                    // Xh/Xl + rowsum
    matvec01_kernel<<<dim3(CC, BB, 2), 256>>>();                  // u, w
    gram_wmma_kernel<<<dim3(3, KSPLIT, BB), 256, GRAM_SMEM>>>();  // <- profiled slot
    reduceG_kernel<<<BB*CC*CC/256, 256>>>();
    gemm256_nt_kernel<<<dim3(4, 4, BB), 256>>>(0);   // P = Aq @ G
    gemm256_nt_kernel<<<dim3(4, 4, BB), 256>>>(1);   // L = P @ Ak^T + rank-1
    softmax_kernel<<<dim3(CC, BB), 256>>>();         // attn + cv fused
    gemm256_nt_kernel<<<dim3(4, 4, BB), 256>>>(2);   // Mh/Ml = attn @ Av + I (pre-split)
    out_wmma_kernel<<<dim3(SS/128, CC/128, BB), 256, OUT_SMEM>>>(out);
}